// round 2
// baseline (speedup 1.0000x reference)
#include <cuda_runtime.h>
#include <cuda_bf16.h>

// ---------------------------------------------------------------------------
// NT-Xent loss, N=8192, D=512 via mma.sync (base sm_103 ISA; tcgen05 is
// rejected by this toolchain's PTX target).
// loss_i = (1 - pos_i)/tau + log( sum_{j != i} exp((dot_ij - 1)/tau) )
// fixed softmax max = 1/tau since rows are unit-norm.
// ---------------------------------------------------------------------------

#define NN      8192
#define DD      512
#define BHALF   4096
#define BM      128
#define BK      64
#define NCHUNK  8            // 512/64
#define NSLICE  2
#define TPS     32           // column tiles per slice

#define K1F     20.60992915555662f     // log2(e)/0.07
#define INV_TAU 14.285714285714286f

#define A_BYTES  131072      // 128 rows x 512 cols bf16 (8 chunks x 16 KB)
#define B_OFF    131072
#define B_BYTES  16384       // 128 x 64 bf16
#define SMEM_BYTES (A_BYTES + 2*B_BYTES + 1024)

__device__ __align__(128) __nv_bfloat16 g_z[(size_t)NN * DD];
__device__ float g_partial[4 * NN];   // [slice*2 + warpN][row]
__device__ float g_pos[NN];

// ------------------------------- helpers -----------------------------------
__device__ __forceinline__ unsigned smem_u32(const void* p) {
    unsigned a;
    asm("{ .reg .u64 t; cvta.to.shared.u64 t, %1; cvt.u32.u64 %0, t; }"
        : "=r"(a) : "l"(p));
    return a;
}
__device__ __forceinline__ unsigned swz(unsigned off) {
    return off ^ ((off >> 3) & 0x70);
}
__device__ __forceinline__ void cp16(unsigned dst, const void* src) {
    asm volatile("cp.async.cg.shared.global [%0], [%1], 16;"
                 :: "r"(dst), "l"(src) : "memory");
}
#define CP_COMMIT() asm volatile("cp.async.commit_group;" ::: "memory")
#define CP_WAIT(n)  asm volatile("cp.async.wait_group %0;" :: "n"(n) : "memory")

__device__ __forceinline__ void ldsm_x4(unsigned* r, unsigned addr) {
    asm volatile("ldmatrix.sync.aligned.m8n8.x4.shared.b16 {%0,%1,%2,%3}, [%4];"
                 : "=r"(r[0]), "=r"(r[1]), "=r"(r[2]), "=r"(r[3]) : "r"(addr));
}
__device__ __forceinline__ void mma16816(float* c, const unsigned* a,
                                         unsigned b0, unsigned b1) {
    asm volatile(
        "mma.sync.aligned.m16n8k16.row.col.f32.bf16.bf16.f32 "
        "{%0,%1,%2,%3}, {%4,%5,%6,%7}, {%8,%9}, {%0,%1,%2,%3};"
        : "+f"(c[0]), "+f"(c[1]), "+f"(c[2]), "+f"(c[3])
        : "r"(a[0]), "r"(a[1]), "r"(a[2]), "r"(a[3]), "r"(b0), "r"(b1));
}
__device__ __forceinline__ float ex2f(float v) {
    float y;
    asm("ex2.approx.ftz.f32 %0, %1;" : "=f"(y) : "f"(fmaf(v, K1F, -K1F)));
    return y;
}

// ------------------------- kernel 1: normalize -----------------------------
__global__ __launch_bounds__(256) void ntx_normalize(const float* __restrict__ anchor,
                                                     const float* __restrict__ positive) {
    int row  = blockIdx.x * 8 + (threadIdx.x >> 5);
    int lane = threadIdx.x & 31;
    const float* src = (row < BHALF) ? (anchor + (size_t)row * DD)
                                     : (positive + (size_t)(row - BHALF) * DD);
    const float4* s4 = (const float4*)src;
    float4 v[4];
    float ss = 0.f;
#pragma unroll
    for (int q = 0; q < 4; q++) {
        v[q] = s4[lane + 32 * q];
        ss += v[q].x * v[q].x + v[q].y * v[q].y + v[q].z * v[q].z + v[q].w * v[q].w;
    }
#pragma unroll
    for (int o = 16; o > 0; o >>= 1) ss += __shfl_xor_sync(0xFFFFFFFFu, ss, o);
    float inv = 1.0f / fmaxf(sqrtf(ss), 1e-8f);

    __nv_bfloat162* zp = (__nv_bfloat162*)(g_z + (size_t)row * DD);
#pragma unroll
    for (int q = 0; q < 4; q++) {
        int b = (lane + 32 * q) * 2;
        zp[b]     = __floats2bfloat162_rn(v[q].x * inv, v[q].y * inv);
        zp[b + 1] = __floats2bfloat162_rn(v[q].z * inv, v[q].w * inv);
    }
}

// ------------------------- kernel 2: GEMM + exp-reduce ---------------------
__device__ __forceinline__ void issueB(unsigned bbase, int colbase, int k, int tid) {
#pragma unroll
    for (int it = 0; it < 4; it++) {
        int idx = tid + it * 256;
        int r = idx >> 3, c8 = idx & 7;
        const void* src = g_z + ((size_t)(colbase + r) << 9) + k * BK + c8 * 8;
        cp16(bbase + swz((unsigned)(r * 128 + c8 * 16)), src);
    }
}

__global__ __launch_bounds__(256, 1) void ntx_main() {
    extern __shared__ char smem_raw[];
    unsigned raw  = smem_u32(smem_raw);
    unsigned base = (raw + 1023u) & ~1023u;
    unsigned A  = base;
    unsigned Bb = base + B_OFF;

    int tid  = threadIdx.x;
    int wid  = tid >> 5, lane = tid & 31;
    int warpM = wid & 3, warpN = wid >> 2;     // 4 x 2 warp grid, tile 32x64
    int rb = blockIdx.x >> 1, slice = blockIdx.x & 1;
    int rowbase = rb << 7;

    // Resident A tile: rows [rowbase, rowbase+128), K=512, 8 SW128 chunks.
#pragma unroll
    for (int it = 0; it < 32; it++) {
        int idx = tid + it * 256;
        int r = idx >> 6, u = idx & 63, ck = u >> 3, c8 = u & 7;
        const void* src = g_z + ((size_t)(rowbase + r) << 9) + ck * BK + c8 * 8;
        cp16(A + ck * 16384 + swz((unsigned)(r * 128 + c8 * 16)), src);
    }
    CP_COMMIT();

    int t0colbase = ((slice << 5) + 0) << 7;
    issueB(Bb, t0colbase, 0, tid);
    CP_COMMIT();

    // fragment address components (same swizzle xor for A and B: lr<<4)
    int sel = lane >> 3, lr = lane & 7;
    unsigned sx = (unsigned)(lr << 4);
    int arow = warpM * 32 + ((sel & 1) << 3) + lr;
    unsigned aoff[2][4];
#pragma unroll
    for (int mf = 0; mf < 2; mf++)
#pragma unroll
        for (int ks = 0; ks < 4; ks++)
            aoff[mf][ks] = (unsigned)((arow + 16 * mf) * 128)
                         + ((unsigned)((2 * ks + (sel >> 1)) * 16) ^ sx);
    int browb = warpN * 64 + ((sel >> 1) << 3) + lr;
    unsigned boff[4][4];
#pragma unroll
    for (int p = 0; p < 4; p++)
#pragma unroll
        for (int ks = 0; ks < 4; ks++)
            boff[p][ks] = (unsigned)((browb + 16 * p) * 128)
                        + ((unsigned)((2 * ks + (sel & 1)) * 16) ^ sx);

    float acc[2][8][4];
    float rsum[2][2] = {{0.f, 0.f}, {0.f, 0.f}};
    int qrow = lane >> 2;                       // row-within-8 owned by this thread

    for (int t = 0; t < TPS; t++) {
        int colbase = ((slice << 5) + t) << 7;
#pragma unroll
        for (int mf = 0; mf < 2; mf++)
#pragma unroll
            for (int nf = 0; nf < 8; nf++)
#pragma unroll
                for (int e = 0; e < 4; e++) acc[mf][nf][e] = 0.f;

        for (int k = 0; k < NCHUNK; k++) {
            int b = k & 1;
            bool last = (k == NCHUNK - 1) && (t == TPS - 1);
            if (k < NCHUNK - 1)
                issueB(Bb + ((k + 1) & 1) * B_BYTES, colbase, k + 1, tid);
            else if (t + 1 < TPS)
                issueB(Bb, ((slice << 5) + t + 1) << 7, 0, tid);
            CP_COMMIT();
            if (last) CP_WAIT(0); else CP_WAIT(1);
            __syncthreads();

            unsigned Ac = A + k * 16384;
            unsigned Bc = Bb + b * B_BYTES;
#pragma unroll
            for (int ks = 0; ks < 4; ks++) {
                unsigned afr[2][4];
                ldsm_x4(afr[0], Ac + aoff[0][ks]);
                ldsm_x4(afr[1], Ac + aoff[1][ks]);
                unsigned bfr[4][4];
#pragma unroll
                for (int p = 0; p < 4; p++) ldsm_x4(bfr[p], Bc + boff[p][ks]);
#pragma unroll
                for (int mf = 0; mf < 2; mf++)
#pragma unroll
                    for (int nf = 0; nf < 8; nf++)
                        mma16816(acc[mf][nf], afr[mf],
                                 bfr[nf >> 1][(nf & 1) * 2],
                                 bfr[nf >> 1][(nf & 1) * 2 + 1]);
            }
            __syncthreads();
        }

        // ---- epilogue: exp + per-row accumulate (registers only) ----
#pragma unroll
        for (int mf = 0; mf < 2; mf++) {
            float slo = 0.f, shi = 0.f;
#pragma unroll
            for (int nf = 0; nf < 8; nf++) {
                slo += ex2f(acc[mf][nf][0]) + ex2f(acc[mf][nf][1]);
                shi += ex2f(acc[mf][nf][2]) + ex2f(acc[mf][nf][3]);
            }
            rsum[mf][0] += slo;
            rsum[mf][1] += shi;
        }

        bool isdiag = (colbase == rowbase);
        bool ispos  = (colbase == ((rowbase + BHALF) & (NN - 1)));
        if (isdiag | ispos) {
#pragma unroll
            for (int mf = 0; mf < 2; mf++)
#pragma unroll
                for (int h = 0; h < 2; h++) {
                    int rloc = warpM * 32 + mf * 16 + h * 8 + qrow;
                    int c = rloc - warpN * 64;     // target local col == rloc
                    if (c >= 0 && c < 64 && (((c >> 1) & 3) == (lane & 3))) {
                        float v = acc[mf][c >> 3][(h << 1) | (c & 1)];
                        if (isdiag) rsum[mf][h] -= ex2f(v);     // drop self term
                        if (ispos)  g_pos[rowbase + rloc] = v;  // raw pos dot
                    }
                }
        }
    }

    // ---- final per-row reduction: quad shuffle, then indexed store ----
#pragma unroll
    for (int mf = 0; mf < 2; mf++)
#pragma unroll
        for (int h = 0; h < 2; h++) {
            float v = rsum[mf][h];
            v += __shfl_xor_sync(0xFFFFFFFFu, v, 1);
            v += __shfl_xor_sync(0xFFFFFFFFu, v, 2);
            if ((lane & 3) == 0) {
                int row = rowbase + warpM * 32 + mf * 16 + h * 8 + qrow;
                g_partial[(slice * 2 + warpN) * NN + row] = v;
            }
        }
}

// ------------------------- kernel 3: final reduce --------------------------
__global__ __launch_bounds__(1024) void ntx_final(float* __restrict__ out) {
    int tid = threadIdx.x;
    float local = 0.f;
    for (int r = tid; r < NN; r += 1024) {
        float s = g_partial[r] + g_partial[NN + r]
                + g_partial[2 * NN + r] + g_partial[3 * NN + r];
        local += (1.0f - g_pos[r]) * INV_TAU + logf(s);
    }
#pragma unroll
    for (int o = 16; o > 0; o >>= 1) local += __shfl_xor_sync(0xFFFFFFFFu, local, o);
    __shared__ float red[32];
    if ((tid & 31) == 0) red[tid >> 5] = local;
    __syncthreads();
    if (tid < 32) {
        float v = (tid < 32) ? red[tid] : 0.f;
#pragma unroll
        for (int o = 16; o > 0; o >>= 1) v += __shfl_xor_sync(0xFFFFFFFFu, v, o);
        if (tid == 0) out[0] = v * (1.0f / (float)NN);
    }
}

// ---------------------------------------------------------------------------
extern "C" void kernel_launch(void* const* d_in, const int* in_sizes, int n_in,
                              void* d_out, int out_size) {
    (void)in_sizes; (void)n_in; (void)out_size;
    const float* anchor   = (const float*)d_in[0];
    const float* positive = (const float*)d_in[1];

    static int configured = 0;
    cudaFuncSetAttribute(ntx_main, cudaFuncAttributeMaxDynamicSharedMemorySize,
                         SMEM_BYTES);
    (void)configured;

    ntx_normalize<<<NN / 8, 256>>>(anchor, positive);
    ntx_main<<<64 * NSLICE, 256, SMEM_BYTES>>>();
    ntx_final<<<1, 1024>>>((float*)d_out);
}

// round 3
// speedup vs baseline: 1.7283x; 1.7283x over previous
#include <cuda_runtime.h>
#include <cuda_bf16.h>

// ---------------------------------------------------------------------------
// NT-Xent loss, N=8192, D=512 via mma.sync, exploiting symmetry of S = Z Z^T:
// only upper-triangular 128x128 block tiles are computed. Tile (I,J), J>I,
// contributes exp-row-sums to block I rows and exp-col-sums to block J rows.
// loss_i = (1 - pos_i)/tau + log( sum_{j != i} exp((dot_ij - 1)/tau) )
// ---------------------------------------------------------------------------

#define NN      8192
#define DD      512
#define BHALF   4096
#define BK      64
#define NCHUNK  8            // 512/64

#define K1F     20.60992915555662f     // log2(e)/0.07
#define INV_TAU 14.285714285714286f

#define A_BYTES  131072      // 128 rows x 512 cols bf16 (8 chunks x 16 KB)
#define B_OFF    131072
#define B_BYTES  16384       // 128 x 64 bf16
#define SMEM_BYTES (A_BYTES + 2*B_BYTES + 1024)

__device__ __align__(128) __nv_bfloat16 g_z[(size_t)NN * DD];
__device__ float g_rowsum[NN];
__device__ float g_pos[NN];

// ------------------------------- helpers -----------------------------------
__device__ __forceinline__ unsigned smem_u32(const void* p) {
    unsigned a;
    asm("{ .reg .u64 t; cvta.to.shared.u64 t, %1; cvt.u32.u64 %0, t; }"
        : "=r"(a) : "l"(p));
    return a;
}
__device__ __forceinline__ unsigned swz(unsigned off) {
    return off ^ ((off >> 3) & 0x70);
}
__device__ __forceinline__ void cp16(unsigned dst, const void* src) {
    asm volatile("cp.async.cg.shared.global [%0], [%1], 16;"
                 :: "r"(dst), "l"(src) : "memory");
}
#define CP_COMMIT() asm volatile("cp.async.commit_group;" ::: "memory")
#define CP_WAIT(n)  asm volatile("cp.async.wait_group %0;" :: "n"(n) : "memory")

__device__ __forceinline__ void ldsm_x4(unsigned* r, unsigned addr) {
    asm volatile("ldmatrix.sync.aligned.m8n8.x4.shared.b16 {%0,%1,%2,%3}, [%4];"
                 : "=r"(r[0]), "=r"(r[1]), "=r"(r[2]), "=r"(r[3]) : "r"(addr));
}
__device__ __forceinline__ void mma16816(float* c, const unsigned* a,
                                         unsigned b0, unsigned b1) {
    asm volatile(
        "mma.sync.aligned.m16n8k16.row.col.f32.bf16.bf16.f32 "
        "{%0,%1,%2,%3}, {%4,%5,%6,%7}, {%8,%9}, {%0,%1,%2,%3};"
        : "+f"(c[0]), "+f"(c[1]), "+f"(c[2]), "+f"(c[3])
        : "r"(a[0]), "r"(a[1]), "r"(a[2]), "r"(a[3]), "r"(b0), "r"(b1));
}
__device__ __forceinline__ float ex2f(float v) {
    float y;
    asm("ex2.approx.ftz.f32 %0, %1;" : "=f"(y) : "f"(fmaf(v, K1F, -K1F)));
    return y;
}

// ------------------------- kernel 1: normalize (+ zero rowsum) -------------
__global__ __launch_bounds__(256) void ntx_normalize(const float* __restrict__ anchor,
                                                     const float* __restrict__ positive) {
    int gt = blockIdx.x * 256 + threadIdx.x;
    if (gt < NN) g_rowsum[gt] = 0.f;          // graph-replay safe re-init

    int row  = blockIdx.x * 8 + (threadIdx.x >> 5);
    int lane = threadIdx.x & 31;
    const float* src = (row < BHALF) ? (anchor + (size_t)row * DD)
                                     : (positive + (size_t)(row - BHALF) * DD);
    const float4* s4 = (const float4*)src;
    float4 v[4];
    float ss = 0.f;
#pragma unroll
    for (int q = 0; q < 4; q++) {
        v[q] = s4[lane + 32 * q];
        ss += v[q].x * v[q].x + v[q].y * v[q].y + v[q].z * v[q].z + v[q].w * v[q].w;
    }
#pragma unroll
    for (int o = 16; o > 0; o >>= 1) ss += __shfl_xor_sync(0xFFFFFFFFu, ss, o);
    float inv = 1.0f / fmaxf(sqrtf(ss), 1e-8f);

    __nv_bfloat162* zp = (__nv_bfloat162*)(g_z + (size_t)row * DD);
#pragma unroll
    for (int q = 0; q < 4; q++) {
        int b = (lane + 32 * q) * 2;
        zp[b]     = __floats2bfloat162_rn(v[q].x * inv, v[q].y * inv);
        zp[b + 1] = __floats2bfloat162_rn(v[q].z * inv, v[q].w * inv);
    }
}

// ------------------------- kernel 2: upper-tri GEMM + exp-reduce -----------
__device__ __forceinline__ void issueB(unsigned bbase, int colbase, int k, int tid) {
#pragma unroll
    for (int it = 0; it < 4; it++) {
        int idx = tid + it * 256;
        int r = idx >> 3, c8 = idx & 7;
        const void* src = g_z + ((size_t)(colbase + r) << 9) + k * BK + c8 * 8;
        cp16(bbase + swz((unsigned)(r * 128 + c8 * 16)), src);
    }
}

__global__ __launch_bounds__(256, 1) void ntx_main() {
    extern __shared__ char smem_raw[];
    unsigned raw  = smem_u32(smem_raw);
    unsigned base = (raw + 1023u) & ~1023u;
    unsigned A  = base;
    unsigned Bb = base + B_OFF;

    int tid  = threadIdx.x;
    int wid  = tid >> 5, lane = tid & 31;
    int warpM = wid & 3, warpN = wid >> 2;     // 4 x 2 warp grid, tile 32x64
    int qrow = lane >> 2;

    int pairc = blockIdx.x >> 2;               // 0..31
    int sl    = blockIdx.x & 3;
    const int sb0 = (sl == 0) ? 0  : (sl == 1) ? 17 : (sl == 2) ? 33 : 49;
    const int sb1 = (sl == 0) ? 17 : (sl == 1) ? 33 : (sl == 2) ? 49 : 65;
    int n1 = 64 - pairc;                       // phase-1 tile count of this pair

    // fragment address components (same swizzle xor for A and B: lr<<4)
    int sel = lane >> 3, lr = lane & 7;
    unsigned sx = (unsigned)(lr << 4);
    int arow = warpM * 32 + ((sel & 1) << 3) + lr;
    unsigned aoff[2][4];
#pragma unroll
    for (int mf = 0; mf < 2; mf++)
#pragma unroll
        for (int ks = 0; ks < 4; ks++)
            aoff[mf][ks] = (unsigned)((arow + 16 * mf) * 128)
                         + ((unsigned)((2 * ks + (sel >> 1)) * 16) ^ sx);
    int browb = warpN * 64 + ((sel >> 1) << 3) + lr;
    unsigned boff[4][4];
#pragma unroll
    for (int p = 0; p < 4; p++)
#pragma unroll
        for (int ks = 0; ks < 4; ks++)
            boff[p][ks] = (unsigned)((browb + 16 * p) * 128)
                        + ((unsigned)((2 * ks + (sel & 1)) * 16) ^ sx);

    float acc[2][8][4];
    float rsum[2][2] = {{0.f, 0.f}, {0.f, 0.f}};
    int  curI = -1;
    bool have0 = false;

    for (int idx = sb0; idx < sb1; idx++) {
        int I, J;
        if (idx < n1) { I = pairc;      J = pairc + idx; }
        else          { I = 63 - pairc; J = I + (idx - n1); }
        int rowbase = I << 7, colbase = J << 7;

        if (I != curI) {
            if (curI >= 0) {
                // flush row partial sums of finished phase
#pragma unroll
                for (int mf = 0; mf < 2; mf++)
#pragma unroll
                    for (int h = 0; h < 2; h++) {
                        float v = rsum[mf][h];
                        v += __shfl_xor_sync(0xFFFFFFFFu, v, 1);
                        v += __shfl_xor_sync(0xFFFFFFFFu, v, 2);
                        if ((lane & 3) == 0)
                            atomicAdd(&g_rowsum[(curI << 7) + warpM * 32 + mf * 16 + h * 8 + qrow], v);
                        rsum[mf][h] = 0.f;
                    }
            }
            CP_WAIT(0);
            // load resident A tile: rows [rowbase, rowbase+128), 8 SW128 chunks
#pragma unroll
            for (int it = 0; it < 32; it++) {
                int x = tid + it * 256;
                int r = x >> 6, u = x & 63, ck = u >> 3, c8 = u & 7;
                const void* src = g_z + ((size_t)(rowbase + r) << 9) + ck * BK + c8 * 8;
                cp16(A + ck * 16384 + swz((unsigned)(r * 128 + c8 * 16)), src);
            }
            CP_COMMIT();
            curI = I;
            have0 = false;
        }
        if (!have0) { issueB(Bb, colbase, 0, tid); CP_COMMIT(); }

        // prefetch target: next tile in this slice if it shares I
        int nextcol = -1;
        if (idx + 1 < sb1) {
            int I2, J2;
            if (idx + 1 < n1) { I2 = pairc;      J2 = pairc + idx + 1; }
            else              { I2 = 63 - pairc; J2 = I2 + (idx + 1 - n1); }
            if (I2 == I) nextcol = J2 << 7;
        }

#pragma unroll
        for (int mf = 0; mf < 2; mf++)
#pragma unroll
            for (int nf = 0; nf < 8; nf++)
#pragma unroll
                for (int e = 0; e < 4; e++) acc[mf][nf][e] = 0.f;

        for (int k = 0; k < NCHUNK; k++) {
            int b = k & 1;
            if (k < NCHUNK - 1)      issueB(Bb + ((k + 1) & 1) * B_BYTES, colbase, k + 1, tid);
            else if (nextcol >= 0)   issueB(Bb, nextcol, 0, tid);
            CP_COMMIT();
            CP_WAIT(1);
            __syncthreads();

            unsigned Ac = A + k * 16384;
            unsigned Bc = Bb + b * B_BYTES;
#pragma unroll
            for (int ks = 0; ks < 4; ks++) {
                unsigned afr[2][4];
                ldsm_x4(afr[0], Ac + aoff[0][ks]);
                ldsm_x4(afr[1], Ac + aoff[1][ks]);
                unsigned bfr[4][4];
#pragma unroll
                for (int p = 0; p < 4; p++) ldsm_x4(bfr[p], Bc + boff[p][ks]);
#pragma unroll
                for (int mf = 0; mf < 2; mf++)
#pragma unroll
                    for (int nf = 0; nf < 8; nf++)
                        mma16816(acc[mf][nf], afr[mf],
                                 bfr[nf >> 1][(nf & 1) * 2],
                                 bfr[nf >> 1][(nf & 1) * 2 + 1]);
            }
            __syncthreads();
        }
        have0 = (nextcol >= 0);

        // ---- epilogue ----
        bool isdiag = (J == I);
        bool ispos  = (J == I + 32);

        // raw-value extraction (diag self-term, positive logits)
        if (isdiag | ispos) {
#pragma unroll
            for (int mf = 0; mf < 2; mf++)
#pragma unroll
                for (int h = 0; h < 2; h++) {
                    int rloc = warpM * 32 + mf * 16 + h * 8 + qrow;
                    int c = rloc - warpN * 64;
                    if (c >= 0 && c < 64 && (((c >> 1) & 3) == (lane & 3))) {
                        float v = acc[mf][c >> 3][(h << 1) | (c & 1)];
                        if (isdiag) rsum[mf][h] -= ex2f(v);
                        if (ispos) {
                            g_pos[rowbase + rloc] = v;
                            g_pos[rowbase + rloc + BHALF] = v;
                        }
                    }
                }
        }

        // exp + row partials (registers) + column partials
        float colp[16];
#pragma unroll
        for (int q = 0; q < 16; q++) colp[q] = 0.f;
#pragma unroll
        for (int mf = 0; mf < 2; mf++) {
            float slo = 0.f, shi = 0.f;
#pragma unroll
            for (int nf = 0; nf < 8; nf++) {
                float e0 = ex2f(acc[mf][nf][0]);
                float e1 = ex2f(acc[mf][nf][1]);
                float e2 = ex2f(acc[mf][nf][2]);
                float e3 = ex2f(acc[mf][nf][3]);
                slo += e0 + e1;
                shi += e2 + e3;
                colp[nf * 2]     += e0 + e2;
                colp[nf * 2 + 1] += e1 + e3;
            }
            rsum[mf][0] += slo;
            rsum[mf][1] += shi;
        }

        // column sums -> rows of block J (transpose contribution); skip diag
        if (!isdiag) {
#pragma unroll
            for (int q = 0; q < 16; q++) {
                float v = colp[q];
                v += __shfl_xor_sync(0xFFFFFFFFu, v, 4);
                v += __shfl_xor_sync(0xFFFFFFFFu, v, 8);
                v += __shfl_xor_sync(0xFFFFFFFFu, v, 16);
                if (lane < 4) {
                    int ccol = (q >> 1) * 8 + 2 * lane + (q & 1);
                    atomicAdd(&g_rowsum[colbase + warpN * 64 + ccol], v);
                }
            }
        }
    }

    // final row flush
#pragma unroll
    for (int mf = 0; mf < 2; mf++)
#pragma unroll
        for (int h = 0; h < 2; h++) {
            float v = rsum[mf][h];
            v += __shfl_xor_sync(0xFFFFFFFFu, v, 1);
            v += __shfl_xor_sync(0xFFFFFFFFu, v, 2);
            if ((lane & 3) == 0 && curI >= 0)
                atomicAdd(&g_rowsum[(curI << 7) + warpM * 32 + mf * 16 + h * 8 + qrow], v);
        }
}

// ------------------------- kernel 3: final reduce --------------------------
__global__ __launch_bounds__(1024) void ntx_final(float* __restrict__ out) {
    int tid = threadIdx.x;
    float local = 0.f;
    for (int r = tid; r < NN; r += 1024) {
        local += (1.0f - g_pos[r]) * INV_TAU + logf(g_rowsum[r]);
    }
#pragma unroll
    for (int o = 16; o > 0; o >>= 1) local += __shfl_xor_sync(0xFFFFFFFFu, local, o);
    __shared__ float red[32];
    if ((tid & 31) == 0) red[tid >> 5] = local;
    __syncthreads();
    if (tid < 32) {
        float v = red[tid];
#pragma unroll
        for (int o = 16; o > 0; o >>= 1) v += __shfl_xor_sync(0xFFFFFFFFu, v, o);
        if (tid == 0) out[0] = v * (1.0f / (float)NN);
    }
}

// ---------------------------------------------------------------------------
extern "C" void kernel_launch(void* const* d_in, const int* in_sizes, int n_in,
                              void* d_out, int out_size) {
    (void)in_sizes; (void)n_in; (void)out_size;
    const float* anchor   = (const float*)d_in[0];
    const float* positive = (const float*)d_in[1];

    cudaFuncSetAttribute(ntx_main, cudaFuncAttributeMaxDynamicSharedMemorySize,
                         SMEM_BYTES);

    ntx_normalize<<<NN / 8, 256>>>(anchor, positive);
    ntx_main<<<128, 256, SMEM_BYTES>>>();
    ntx_final<<<1, 1024>>>((float*)d_out);
}

// round 4
// speedup vs baseline: 2.1450x; 1.2411x over previous
#include <cuda_runtime.h>
#include <cuda_bf16.h>

// ---------------------------------------------------------------------------
// NT-Xent loss, N=8192, D=512. FP8 (e4m3, scale 16) mma.sync m16n8k32,
// upper-triangular block tiles only (S = Z Z^T symmetric).
// Tile (I,J), J>I: exp-row-sums -> rows of block I, exp-col-sums -> block J.
// loss_i = (1 - pos_i)/tau + log( sum_{j != i} exp((dot_ij - 1)/tau) )
// ---------------------------------------------------------------------------

#define NN      8192
#define DD      512
#define BHALF   4096
#define NCHUNK  4            // 512 fp8 bytes / 128-byte chunk

#define K1F     20.60992915555662f        // log2(e)/0.07
#define EXSC    0.08050753576389304f      // K1F / 256   (fp8 scale^2)
#define PSC     0.00390625f               // 1/256
#define INV_TAU 14.285714285714286f

#define A_BYTES  65536       // 128 rows x 512 B (4 chunks x 16 KB)
#define B_OFF    65536
#define B_BYTES  16384       // 128 rows x 128 B
#define SMEM_BYTES (A_BYTES + 2*B_BYTES + 1024)

__device__ __align__(128) unsigned char g_z[(size_t)NN * DD];   // e4m3, x16
__device__ float g_rowsum[NN];
__device__ float g_pos[NN];

// ------------------------------- helpers -----------------------------------
__device__ __forceinline__ unsigned smem_u32(const void* p) {
    unsigned a;
    asm("{ .reg .u64 t; cvta.to.shared.u64 t, %1; cvt.u32.u64 %0, t; }"
        : "=r"(a) : "l"(p));
    return a;
}
__device__ __forceinline__ unsigned swz(unsigned off) {
    return off ^ ((off >> 3) & 0x70);
}
__device__ __forceinline__ void cp16(unsigned dst, const void* src) {
    asm volatile("cp.async.cg.shared.global [%0], [%1], 16;"
                 :: "r"(dst), "l"(src) : "memory");
}
#define CP_COMMIT() asm volatile("cp.async.commit_group;" ::: "memory")
#define CP_WAIT(n)  asm volatile("cp.async.wait_group %0;" :: "n"(n) : "memory")

__device__ __forceinline__ void ldsm_x4(unsigned* r, unsigned addr) {
    asm volatile("ldmatrix.sync.aligned.m8n8.x4.shared.b16 {%0,%1,%2,%3}, [%4];"
                 : "=r"(r[0]), "=r"(r[1]), "=r"(r[2]), "=r"(r[3]) : "r"(addr));
}
__device__ __forceinline__ void mma_fp8(float* c, const unsigned* a,
                                        unsigned b0, unsigned b1) {
    asm volatile(
        "mma.sync.aligned.m16n8k32.row.col.f32.e4m3.e4m3.f32 "
        "{%0,%1,%2,%3}, {%4,%5,%6,%7}, {%8,%9}, {%0,%1,%2,%3};"
        : "+f"(c[0]), "+f"(c[1]), "+f"(c[2]), "+f"(c[3])
        : "r"(a[0]), "r"(a[1]), "r"(a[2]), "r"(a[3]), "r"(b0), "r"(b1));
}
__device__ __forceinline__ float ex2s(float v) {   // exp((v/256 - 1)/tau)
    float y;
    asm("ex2.approx.ftz.f32 %0, %1;" : "=f"(y) : "f"(fmaf(v, EXSC, -K1F)));
    return y;
}
__device__ __forceinline__ unsigned short cvt2_e4m3(float lo, float hi) {
    unsigned short r;
    asm("cvt.rn.satfinite.e4m3x2.f32 %0, %1, %2;" : "=h"(r) : "f"(hi), "f"(lo));
    return r;
}

// ------------------------- kernel 1: normalize -> fp8 ----------------------
__global__ __launch_bounds__(256) void ntx_normalize(const float* __restrict__ anchor,
                                                     const float* __restrict__ positive) {
    int gt = blockIdx.x * 256 + threadIdx.x;
    if (gt < NN) g_rowsum[gt] = 0.f;          // graph-replay safe re-init

    int row  = blockIdx.x * 8 + (threadIdx.x >> 5);
    int lane = threadIdx.x & 31;
    const float* src = (row < BHALF) ? (anchor + (size_t)row * DD)
                                     : (positive + (size_t)(row - BHALF) * DD);
    const float4* s4 = (const float4*)src;
    float4 v[4];
    float ss = 0.f;
#pragma unroll
    for (int q = 0; q < 4; q++) {
        v[q] = s4[lane + 32 * q];
        ss += v[q].x * v[q].x + v[q].y * v[q].y + v[q].z * v[q].z + v[q].w * v[q].w;
    }
#pragma unroll
    for (int o = 16; o > 0; o >>= 1) ss += __shfl_xor_sync(0xFFFFFFFFu, ss, o);
    float s16 = 16.0f / fmaxf(sqrtf(ss), 1e-8f);   // unit-norm then x16 for e4m3

    unsigned* zp = (unsigned*)(g_z + (size_t)row * DD);
#pragma unroll
    for (int q = 0; q < 4; q++) {
        unsigned lo = cvt2_e4m3(v[q].x * s16, v[q].y * s16);
        unsigned hi = cvt2_e4m3(v[q].z * s16, v[q].w * s16);
        zp[lane + 32 * q] = lo | (hi << 16);
    }
}

// ------------------------- kernel 2: upper-tri GEMM + exp-reduce -----------
__device__ __forceinline__ void issueB(unsigned bbase, int colbase, int k, int tid) {
#pragma unroll
    for (int it = 0; it < 4; it++) {
        int idx = tid + it * 256;
        int r = idx >> 3, c8 = idx & 7;
        const void* src = g_z + ((size_t)(colbase + r) << 9) + k * 128 + c8 * 16;
        cp16(bbase + swz((unsigned)(r * 128 + c8 * 16)), src);
    }
}

__global__ __launch_bounds__(256, 1) void ntx_main() {
    extern __shared__ char smem_raw[];
    unsigned raw  = smem_u32(smem_raw);
    unsigned base = (raw + 1023u) & ~1023u;
    unsigned A  = base;
    unsigned Bb = base + B_OFF;

    int tid  = threadIdx.x;
    int wid  = tid >> 5, lane = tid & 31;
    int warpM = wid & 3, warpN = wid >> 2;     // 4 x 2 warp grid, tile 32x64
    int qrow = lane >> 2;

    int pairc = blockIdx.x >> 2;               // 0..31
    int sl    = blockIdx.x & 3;
    const int sb0 = (sl == 0) ? 0  : (sl == 1) ? 17 : (sl == 2) ? 33 : 49;
    const int sb1 = (sl == 0) ? 17 : (sl == 1) ? 33 : (sl == 2) ? 49 : 65;
    int n1 = 64 - pairc;                       // phase-1 tile count of this pair

    // ldmatrix lane addressing: sel picks (row+8 | k+16) tile, lr is row-in-8
    int sel = lane >> 3, lr = lane & 7;
    unsigned aoff[2][4];
#pragma unroll
    for (int mf = 0; mf < 2; mf++)
#pragma unroll
        for (int ks = 0; ks < 4; ks++) {
            int r = warpM * 32 + mf * 16 + ((sel & 1) << 3) + lr;
            unsigned cb = (unsigned)(ks * 32 + ((sel >> 1) << 4));
            aoff[mf][ks] = (unsigned)(r * 128) + (cb ^ ((unsigned)lr << 4));
        }
    unsigned boff[4][4];
#pragma unroll
    for (int p = 0; p < 4; p++)
#pragma unroll
        for (int ks = 0; ks < 4; ks++) {
            int r = warpN * 64 + p * 16 + ((sel & 1) << 3) + lr;
            unsigned cb = (unsigned)(ks * 32 + ((sel >> 1) << 4));
            boff[p][ks] = (unsigned)(r * 128) + (cb ^ ((unsigned)lr << 4));
        }

    float acc[2][8][4];
    float rsum[2][2] = {{0.f, 0.f}, {0.f, 0.f}};
    int  curI = -1;
    bool have0 = false;

    for (int idx = sb0; idx < sb1; idx++) {
        int I, J;
        if (idx < n1) { I = pairc;      J = pairc + idx; }
        else          { I = 63 - pairc; J = I + (idx - n1); }
        int rowbase = I << 7, colbase = J << 7;

        if (I != curI) {
            if (curI >= 0) {
#pragma unroll
                for (int mf = 0; mf < 2; mf++)
#pragma unroll
                    for (int h = 0; h < 2; h++) {
                        float v = rsum[mf][h];
                        v += __shfl_xor_sync(0xFFFFFFFFu, v, 1);
                        v += __shfl_xor_sync(0xFFFFFFFFu, v, 2);
                        if ((lane & 3) == 0)
                            atomicAdd(&g_rowsum[(curI << 7) + warpM * 32 + mf * 16 + h * 8 + qrow], v);
                        rsum[mf][h] = 0.f;
                    }
            }
            CP_WAIT(0);
            // resident A tile: 128 rows x 512 B, 4 SW128 chunks
#pragma unroll
            for (int it = 0; it < 16; it++) {
                int x = tid + it * 256;
                int r = x >> 5, u = x & 31, ck = u >> 3, c8 = u & 7;
                const void* src = g_z + ((size_t)(rowbase + r) << 9) + ck * 128 + c8 * 16;
                cp16(A + ck * 16384 + swz((unsigned)(r * 128 + c8 * 16)), src);
            }
            CP_COMMIT();
            curI = I;
            have0 = false;
        }
        if (!have0) { issueB(Bb, colbase, 0, tid); CP_COMMIT(); }

        int nextcol = -1;
        if (idx + 1 < sb1) {
            int I2, J2;
            if (idx + 1 < n1) { I2 = pairc;      J2 = pairc + idx + 1; }
            else              { I2 = 63 - pairc; J2 = I2 + (idx + 1 - n1); }
            if (I2 == I) nextcol = J2 << 7;
        }

#pragma unroll
        for (int mf = 0; mf < 2; mf++)
#pragma unroll
            for (int nf = 0; nf < 8; nf++)
#pragma unroll
                for (int e = 0; e < 4; e++) acc[mf][nf][e] = 0.f;

        for (int k = 0; k < NCHUNK; k++) {
            int b = k & 1;
            if (k < NCHUNK - 1)      issueB(Bb + ((k + 1) & 1) * B_BYTES, colbase, k + 1, tid);
            else if (nextcol >= 0)   issueB(Bb, nextcol, 0, tid);
            CP_COMMIT();
            CP_WAIT(1);
            __syncthreads();

            unsigned Ac = A + k * 16384;
            unsigned Bc = Bb + b * B_BYTES;
#pragma unroll
            for (int ks = 0; ks < 4; ks++) {
                unsigned afr[2][4];
                ldsm_x4(afr[0], Ac + aoff[0][ks]);
                ldsm_x4(afr[1], Ac + aoff[1][ks]);
                unsigned bfr[4][4];
#pragma unroll
                for (int p = 0; p < 4; p++) ldsm_x4(bfr[p], Bc + boff[p][ks]);
#pragma unroll
                for (int mf = 0; mf < 2; mf++)
#pragma unroll
                    for (int nf = 0; nf < 8; nf++)
                        mma_fp8(acc[mf][nf], afr[mf],
                                bfr[nf >> 1][nf & 1],
                                bfr[nf >> 1][2 + (nf & 1)]);
            }
            __syncthreads();
        }
        have0 = (nextcol >= 0);

        // ---- epilogue ----
        bool isdiag = (J == I);
        bool ispos  = (J == I + 32);

        if (isdiag | ispos) {
#pragma unroll
            for (int mf = 0; mf < 2; mf++)
#pragma unroll
                for (int h = 0; h < 2; h++) {
                    int rloc = warpM * 32 + mf * 16 + h * 8 + qrow;
                    int c = rloc - warpN * 64;
                    if (c >= 0 && c < 64 && (((c >> 1) & 3) == (lane & 3))) {
                        float v = acc[mf][c >> 3][(h << 1) | (c & 1)];
                        if (isdiag) rsum[mf][h] -= ex2s(v);
                        if (ispos) {
                            g_pos[rowbase + rloc] = v * PSC;
                            g_pos[rowbase + rloc + BHALF] = v * PSC;
                        }
                    }
                }
        }

        float colp[16];
#pragma unroll
        for (int q = 0; q < 16; q++) colp[q] = 0.f;
#pragma unroll
        for (int mf = 0; mf < 2; mf++) {
            float slo = 0.f, shi = 0.f;
#pragma unroll
            for (int nf = 0; nf < 8; nf++) {
                float e0 = ex2s(acc[mf][nf][0]);
                float e1 = ex2s(acc[mf][nf][1]);
                float e2 = ex2s(acc[mf][nf][2]);
                float e3 = ex2s(acc[mf][nf][3]);
                slo += e0 + e1;
                shi += e2 + e3;
                colp[nf * 2]     += e0 + e2;
                colp[nf * 2 + 1] += e1 + e3;
            }
            rsum[mf][0] += slo;
            rsum[mf][1] += shi;
        }

        if (!isdiag) {
#pragma unroll
            for (int q = 0; q < 16; q++) {
                float v = colp[q];
                v += __shfl_xor_sync(0xFFFFFFFFu, v, 4);
                v += __shfl_xor_sync(0xFFFFFFFFu, v, 8);
                v += __shfl_xor_sync(0xFFFFFFFFu, v, 16);
                if (lane < 4) {
                    int ccol = (q >> 1) * 8 + 2 * lane + (q & 1);
                    atomicAdd(&g_rowsum[colbase + warpN * 64 + ccol], v);
                }
            }
        }
    }

    // final row flush
#pragma unroll
    for (int mf = 0; mf < 2; mf++)
#pragma unroll
        for (int h = 0; h < 2; h++) {
            float v = rsum[mf][h];
            v += __shfl_xor_sync(0xFFFFFFFFu, v, 1);
            v += __shfl_xor_sync(0xFFFFFFFFu, v, 2);
            if ((lane & 3) == 0 && curI >= 0)
                atomicAdd(&g_rowsum[(curI << 7) + warpM * 32 + mf * 16 + h * 8 + qrow], v);
        }
}

// ------------------------- kernel 3: final reduce --------------------------
__global__ __launch_bounds__(1024) void ntx_final(float* __restrict__ out) {
    int tid = threadIdx.x;
    float local = 0.f;
    for (int r = tid; r < NN; r += 1024) {
        local += (1.0f - g_pos[r]) * INV_TAU + logf(g_rowsum[r]);
    }
#pragma unroll
    for (int o = 16; o > 0; o >>= 1) local += __shfl_xor_sync(0xFFFFFFFFu, local, o);
    __shared__ float red[32];
    if ((tid & 31) == 0) red[tid >> 5] = local;
    __syncthreads();
    if (tid < 32) {
        float v = red[tid];
#pragma unroll
        for (int o = 16; o > 0; o >>= 1) v += __shfl_xor_sync(0xFFFFFFFFu, v, o);
        if (tid == 0) out[0] = v * (1.0f / (float)NN);
    }
}

// ---------------------------------------------------------------------------
extern "C" void kernel_launch(void* const* d_in, const int* in_sizes, int n_in,
                              void* d_out, int out_size) {
    (void)in_sizes; (void)n_in; (void)out_size;
    const float* anchor   = (const float*)d_in[0];
    const float* positive = (const float*)d_in[1];

    cudaFuncSetAttribute(ntx_main, cudaFuncAttributeMaxDynamicSharedMemorySize,
                         SMEM_BYTES);

    ntx_normalize<<<NN / 8, 256>>>(anchor, positive);
    ntx_main<<<128, 256, SMEM_BYTES>>>();
    ntx_final<<<1, 1024>>>((float*)d_out);
}

// round 5
// speedup vs baseline: 2.4580x; 1.1459x over previous
#include <cuda_runtime.h>
#include <cuda_bf16.h>

// ---------------------------------------------------------------------------
// NT-Xent loss, N=8192, D=512. FP8 (e4m3, scale 16) mma.sync m16n8k32,
// upper-triangular block tiles only (S = Z Z^T symmetric).
// Tile (I,J), J>I: exp-row-sums -> rows of block I, exp-col-sums -> block J.
// loss_i = (1 - pos_i)/tau + log( sum_{j != i} exp((dot_ij - 1)/tau) )
// 2080 tiles flattened across 148 persistent CTAs (full chip, 1 wave).
// ---------------------------------------------------------------------------

#define NN      8192
#define DD      512
#define BHALF   4096
#define NCHUNK  4            // 512 fp8 bytes / 128-byte chunk
#define NTILES  2080
#define NCTAS   148

#define K1F     20.60992915555662f        // log2(e)/0.07
#define EXSC    0.08050753576389304f      // K1F / 256   (fp8 scale^2)
#define PSC     0.00390625f               // 1/256
#define INV_TAU 14.285714285714286f

#define A_BYTES  65536       // 128 rows x 512 B (4 chunks x 16 KB)
#define B_OFF    65536
#define B_BYTES  16384       // 128 rows x 128 B
#define SMEM_BYTES (A_BYTES + 2*B_BYTES + 1024)

__device__ __align__(128) unsigned char g_z[(size_t)NN * DD];   // e4m3, x16
__device__ float g_rowsum[NN];
__device__ float g_pos[NN];

// ------------------------------- helpers -----------------------------------
__device__ __forceinline__ unsigned smem_u32(const void* p) {
    unsigned a;
    asm("{ .reg .u64 t; cvta.to.shared.u64 t, %1; cvt.u32.u64 %0, t; }"
        : "=r"(a) : "l"(p));
    return a;
}
__device__ __forceinline__ unsigned swz(unsigned off) {
    return off ^ ((off >> 3) & 0x70);
}
__device__ __forceinline__ void cp16(unsigned dst, const void* src) {
    asm volatile("cp.async.cg.shared.global [%0], [%1], 16;"
                 :: "r"(dst), "l"(src) : "memory");
}
#define CP_COMMIT() asm volatile("cp.async.commit_group;" ::: "memory")
#define CP_WAIT(n)  asm volatile("cp.async.wait_group %0;" :: "n"(n) : "memory")

__device__ __forceinline__ void ldsm_x4(unsigned* r, unsigned addr) {
    asm volatile("ldmatrix.sync.aligned.m8n8.x4.shared.b16 {%0,%1,%2,%3}, [%4];"
                 : "=r"(r[0]), "=r"(r[1]), "=r"(r[2]), "=r"(r[3]) : "r"(addr));
}
__device__ __forceinline__ void mma_fp8(float* c, const unsigned* a,
                                        unsigned b0, unsigned b1) {
    asm volatile(
        "mma.sync.aligned.m16n8k32.row.col.f32.e4m3.e4m3.f32 "
        "{%0,%1,%2,%3}, {%4,%5,%6,%7}, {%8,%9}, {%0,%1,%2,%3};"
        : "+f"(c[0]), "+f"(c[1]), "+f"(c[2]), "+f"(c[3])
        : "r"(a[0]), "r"(a[1]), "r"(a[2]), "r"(a[3]), "r"(b0), "r"(b1));
}
__device__ __forceinline__ float ex2s(float v) {   // exp((v/256 - 1)/tau)
    float y;
    asm("ex2.approx.ftz.f32 %0, %1;" : "=f"(y) : "f"(fmaf(v, EXSC, -K1F)));
    return y;
}
__device__ __forceinline__ unsigned short cvt2_e4m3(float lo, float hi) {
    unsigned short r;
    asm("cvt.rn.satfinite.e4m3x2.f32 %0, %1, %2;" : "=h"(r) : "f"(hi), "f"(lo));
    return r;
}

// decode flattened tile index -> (I, J)
__device__ __forceinline__ void tile_decode(int t, int& I, int& J) {
    int p = t / 65;
    int l = t - p * 65;
    int n1 = 64 - p;
    if (l < n1) { I = p;      J = p + l; }
    else        { I = 63 - p; J = I + (l - n1); }
}

// ------------------------- kernel 1: normalize -> fp8 ----------------------
__global__ __launch_bounds__(256) void ntx_normalize(const float* __restrict__ anchor,
                                                     const float* __restrict__ positive) {
    int gt = blockIdx.x * 256 + threadIdx.x;
    if (gt < NN) g_rowsum[gt] = 0.f;          // graph-replay safe re-init

    int row  = blockIdx.x * 8 + (threadIdx.x >> 5);
    int lane = threadIdx.x & 31;
    const float* src = (row < BHALF) ? (anchor + (size_t)row * DD)
                                     : (positive + (size_t)(row - BHALF) * DD);
    const float4* s4 = (const float4*)src;
    float4 v[4];
    float ss = 0.f;
#pragma unroll
    for (int q = 0; q < 4; q++) {
        v[q] = s4[lane + 32 * q];
        ss += v[q].x * v[q].x + v[q].y * v[q].y + v[q].z * v[q].z + v[q].w * v[q].w;
    }
#pragma unroll
    for (int o = 16; o > 0; o >>= 1) ss += __shfl_xor_sync(0xFFFFFFFFu, ss, o);
    float s16 = 16.0f / fmaxf(sqrtf(ss), 1e-8f);   // unit-norm then x16 for e4m3

    unsigned* zp = (unsigned*)(g_z + (size_t)row * DD);
#pragma unroll
    for (int q = 0; q < 4; q++) {
        unsigned lo = cvt2_e4m3(v[q].x * s16, v[q].y * s16);
        unsigned hi = cvt2_e4m3(v[q].z * s16, v[q].w * s16);
        zp[lane + 32 * q] = lo | (hi << 16);
    }
}

// ------------------------- kernel 2: upper-tri GEMM + exp-reduce -----------
__device__ __forceinline__ void issueB(unsigned bbase, int colbase, int k, int tid) {
#pragma unroll
    for (int it = 0; it < 4; it++) {
        int idx = tid + it * 256;
        int r = idx >> 3, c8 = idx & 7;
        const void* src = g_z + ((size_t)(colbase + r) << 9) + k * 128 + c8 * 16;
        cp16(bbase + swz((unsigned)(r * 128 + c8 * 16)), src);
    }
}

__global__ __launch_bounds__(256, 1) void ntx_main() {
    extern __shared__ char smem_raw[];
    unsigned raw  = smem_u32(smem_raw);
    unsigned base = (raw + 1023u) & ~1023u;
    unsigned A  = base;
    unsigned Bb = base + B_OFF;

    int tid  = threadIdx.x;
    int wid  = tid >> 5, lane = tid & 31;
    int warpM = wid & 3, warpN = wid >> 2;     // 4 x 2 warp grid, tile 32x64
    int qrow = lane >> 2;

    int c  = blockIdx.x;
    int t0 = (c * NTILES) / NCTAS;
    int t1 = ((c + 1) * NTILES) / NCTAS;

    // ldmatrix lane addressing: sel picks (row+8 | k+16) tile, lr is row-in-8
    int sel = lane >> 3, lr = lane & 7;
    unsigned aoff[2][4];
#pragma unroll
    for (int mf = 0; mf < 2; mf++)
#pragma unroll
        for (int ks = 0; ks < 4; ks++) {
            int r = warpM * 32 + mf * 16 + ((sel & 1) << 3) + lr;
            unsigned cb = (unsigned)(ks * 32 + ((sel >> 1) << 4));
            aoff[mf][ks] = (unsigned)(r * 128) + (cb ^ ((unsigned)lr << 4));
        }
    unsigned boff[4][4];
#pragma unroll
    for (int p = 0; p < 4; p++)
#pragma unroll
        for (int ks = 0; ks < 4; ks++) {
            int r = warpN * 64 + p * 16 + ((sel & 1) << 3) + lr;
            unsigned cb = (unsigned)(ks * 32 + ((sel >> 1) << 4));
            boff[p][ks] = (unsigned)(r * 128) + (cb ^ ((unsigned)lr << 4));
        }

    float acc[2][8][4];
    float rsum[2][2] = {{0.f, 0.f}, {0.f, 0.f}};
    int  curI = -1;
    bool have0 = false;

    for (int t = t0; t < t1; t++) {
        int I, J;
        tile_decode(t, I, J);
        int rowbase = I << 7, colbase = J << 7;

        if (I != curI) {
            if (curI >= 0) {
#pragma unroll
                for (int mf = 0; mf < 2; mf++)
#pragma unroll
                    for (int h = 0; h < 2; h++) {
                        float v = rsum[mf][h];
                        v += __shfl_xor_sync(0xFFFFFFFFu, v, 1);
                        v += __shfl_xor_sync(0xFFFFFFFFu, v, 2);
                        if ((lane & 3) == 0)
                            atomicAdd(&g_rowsum[(curI << 7) + warpM * 32 + mf * 16 + h * 8 + qrow], v);
                        rsum[mf][h] = 0.f;
                    }
            }
            CP_WAIT(0);
            // resident A tile: 128 rows x 512 B, 4 SW128 chunks
#pragma unroll
            for (int it = 0; it < 16; it++) {
                int x = tid + it * 256;
                int r = x >> 5, u = x & 31, ck = u >> 3, c8 = u & 7;
                const void* src = g_z + ((size_t)(rowbase + r) << 9) + ck * 128 + c8 * 16;
                cp16(A + ck * 16384 + swz((unsigned)(r * 128 + c8 * 16)), src);
            }
            CP_COMMIT();
            curI = I;
            have0 = false;
        }
        if (!have0) { issueB(Bb, colbase, 0, tid); CP_COMMIT(); }

        int nextcol = -1;
        if (t + 1 < t1) {
            int I2, J2;
            tile_decode(t + 1, I2, J2);
            if (I2 == I) nextcol = J2 << 7;
        }

#pragma unroll
        for (int mf = 0; mf < 2; mf++)
#pragma unroll
            for (int nf = 0; nf < 8; nf++)
#pragma unroll
                for (int e = 0; e < 4; e++) acc[mf][nf][e] = 0.f;

        for (int k = 0; k < NCHUNK; k++) {
            int b = k & 1;
            if (k < NCHUNK - 1)      issueB(Bb + ((k + 1) & 1) * B_BYTES, colbase, k + 1, tid);
            else if (nextcol >= 0)   issueB(Bb, nextcol, 0, tid);
            CP_COMMIT();
            CP_WAIT(1);
            __syncthreads();

            unsigned Ac = A + k * 16384;
            unsigned Bc = Bb + b * B_BYTES;
#pragma unroll
            for (int ks = 0; ks < 4; ks++) {
                unsigned afr[2][4];
                ldsm_x4(afr[0], Ac + aoff[0][ks]);
                ldsm_x4(afr[1], Ac + aoff[1][ks]);
                unsigned bfr[4][4];
#pragma unroll
                for (int p = 0; p < 4; p++) ldsm_x4(bfr[p], Bc + boff[p][ks]);
#pragma unroll
                for (int mf = 0; mf < 2; mf++)
#pragma unroll
                    for (int nf = 0; nf < 8; nf++)
                        mma_fp8(acc[mf][nf], afr[mf],
                                bfr[nf >> 1][nf & 1],
                                bfr[nf >> 1][2 + (nf & 1)]);
            }
            __syncthreads();
        }
        have0 = (nextcol >= 0);

        // ---- epilogue ----
        bool isdiag = (J == I);
        bool ispos  = (J == I + 32);

        if (isdiag | ispos) {
#pragma unroll
            for (int mf = 0; mf < 2; mf++)
#pragma unroll
                for (int h = 0; h < 2; h++) {
                    int rloc = warpM * 32 + mf * 16 + h * 8 + qrow;
                    int cc = rloc - warpN * 64;
                    if (cc >= 0 && cc < 64 && (((cc >> 1) & 3) == (lane & 3))) {
                        float v = acc[cc >> 5 ? 1 : 0][0][0];  // placeholder avoided below
                    }
                }
        }
        // (real extraction below — kept in one block for register liveness)
        if (isdiag | ispos) {
#pragma unroll
            for (int mf = 0; mf < 2; mf++)
#pragma unroll
                for (int h = 0; h < 2; h++) {
                    int rloc = warpM * 32 + mf * 16 + h * 8 + qrow;
                    int cc = rloc - warpN * 64;
                    if (cc >= 0 && cc < 64 && (((cc >> 1) & 3) == (lane & 3))) {
                        float v = acc[mf][cc >> 3][(h << 1) | (cc & 1)];
                        if (isdiag) rsum[mf][h] -= ex2s(v);
                        if (ispos) {
                            g_pos[rowbase + rloc] = v * PSC;
                            g_pos[rowbase + rloc + BHALF] = v * PSC;
                        }
                    }
                }
        }

        float colp[16];
#pragma unroll
        for (int q = 0; q < 16; q++) colp[q] = 0.f;
#pragma unroll
        for (int mf = 0; mf < 2; mf++) {
            float slo = 0.f, shi = 0.f;
#pragma unroll
            for (int nf = 0; nf < 8; nf++) {
                float e0 = ex2s(acc[mf][nf][0]);
                float e1 = ex2s(acc[mf][nf][1]);
                float e2 = ex2s(acc[mf][nf][2]);
                float e3 = ex2s(acc[mf][nf][3]);
                slo += e0 + e1;
                shi += e2 + e3;
                colp[nf * 2]     += e0 + e2;
                colp[nf * 2 + 1] += e1 + e3;
            }
            rsum[mf][0] += slo;
            rsum[mf][1] += shi;
        }

        if (!isdiag) {
#pragma unroll
            for (int q = 0; q < 16; q++) {
                float v = colp[q];
                v += __shfl_xor_sync(0xFFFFFFFFu, v, 4);
                v += __shfl_xor_sync(0xFFFFFFFFu, v, 8);
                v += __shfl_xor_sync(0xFFFFFFFFu, v, 16);
                if (lane < 4) {
                    int ccol = (q >> 1) * 8 + 2 * lane + (q & 1);
                    atomicAdd(&g_rowsum[colbase + warpN * 64 + ccol], v);
                }
            }
        }
    }

    // final row flush
#pragma unroll
    for (int mf = 0; mf < 2; mf++)
#pragma unroll
        for (int h = 0; h < 2; h++) {
            float v = rsum[mf][h];
            v += __shfl_xor_sync(0xFFFFFFFFu, v, 1);
            v += __shfl_xor_sync(0xFFFFFFFFu, v, 2);
            if ((lane & 3) == 0 && curI >= 0)
                atomicAdd(&g_rowsum[(curI << 7) + warpM * 32 + mf * 16 + h * 8 + qrow], v);
        }
}

// ------------------------- kernel 3: final reduce --------------------------
__global__ __launch_bounds__(1024) void ntx_final(float* __restrict__ out) {
    int tid = threadIdx.x;
    float local = 0.f;
    for (int r = tid; r < NN; r += 1024) {
        local += (1.0f - g_pos[r]) * INV_TAU + __logf(g_rowsum[r]);
    }
#pragma unroll
    for (int o = 16; o > 0; o >>= 1) local += __shfl_xor_sync(0xFFFFFFFFu, local, o);
    __shared__ float red[32];
    if ((tid & 31) == 0) red[tid >> 5] = local;
    __syncthreads();
    if (tid < 32) {
        float v = red[tid];
#pragma unroll
        for (int o = 16; o > 0; o >>= 1) v += __shfl_xor_sync(0xFFFFFFFFu, v, o);
        if (tid == 0) out[0] = v * (1.0f / (float)NN);
    }
}

// ---------------------------------------------------------------------------
extern "C" void kernel_launch(void* const* d_in, const int* in_sizes, int n_in,
                              void* d_out, int out_size) {
    (void)in_sizes; (void)n_in; (void)out_size;
    const float* anchor   = (const float*)d_in[0];
    const float* positive = (const float*)d_in[1];

    cudaFuncSetAttribute(ntx_main, cudaFuncAttributeMaxDynamicSharedMemorySize,
                         SMEM_BYTES);

    ntx_normalize<<<NN / 8, 256>>>(anchor, positive);
    ntx_main<<<NCTAS, 256, SMEM_BYTES>>>();
    ntx_final<<<1, 1024>>>((float*)d_out);
}

// round 6
// speedup vs baseline: 2.5700x; 1.0455x over previous
#include <cuda_runtime.h>
#include <cuda_bf16.h>

// ---------------------------------------------------------------------------
// NT-Xent loss, N=8192, D=512. FP8 (e4m3, scale 16) mma.sync m16n8k32,
// upper-triangular block tiles only (S = Z Z^T symmetric).
// Tile (I,J), J>I: exp-row-sums -> rows of block I, exp-col-sums -> block J.
// loss_i = (1 - pos_i)/tau + log( sum_{j != i} exp((dot_ij - 1)/tau) )
// 2080 tiles across 148 persistent CTAs; 4-stage cp.async B ring with a
// single __syncthreads per K-chunk and 3-chunk prefetch distance.
// ---------------------------------------------------------------------------

#define NN      8192
#define DD      512
#define BHALF   4096
#define NCHUNK  4            // 512 fp8 bytes / 128-byte chunk; == ring depth
#define NTILES  2080
#define NCTAS   148

#define K1F     20.60992915555662f        // log2(e)/0.07
#define EXSC    0.08050753576389304f      // K1F / 256   (fp8 scale^2)
#define PSC     0.00390625f               // 1/256
#define INV_TAU 14.285714285714286f

#define A_BYTES  65536       // 128 rows x 512 B (4 chunks x 16 KB)
#define B_OFF    65536
#define B_BYTES  16384       // one B chunk: 128 rows x 128 B
#define SMEM_BYTES (A_BYTES + 4*B_BYTES + 1024)

__device__ __align__(128) unsigned char g_z[(size_t)NN * DD];   // e4m3, x16
__device__ float g_rowsum[NN];
__device__ float g_pos[NN];

// ------------------------------- helpers -----------------------------------
__device__ __forceinline__ unsigned smem_u32(const void* p) {
    unsigned a;
    asm("{ .reg .u64 t; cvta.to.shared.u64 t, %1; cvt.u32.u64 %0, t; }"
        : "=r"(a) : "l"(p));
    return a;
}
__device__ __forceinline__ unsigned swz(unsigned off) {
    return off ^ ((off >> 3) & 0x70);
}
__device__ __forceinline__ void cp16(unsigned dst, const void* src) {
    asm volatile("cp.async.cg.shared.global [%0], [%1], 16;"
                 :: "r"(dst), "l"(src) : "memory");
}
#define CP_COMMIT() asm volatile("cp.async.commit_group;" ::: "memory")
#define CP_WAIT(n)  asm volatile("cp.async.wait_group %0;" :: "n"(n) : "memory")

__device__ __forceinline__ void ldsm_x4(unsigned* r, unsigned addr) {
    asm volatile("ldmatrix.sync.aligned.m8n8.x4.shared.b16 {%0,%1,%2,%3}, [%4];"
                 : "=r"(r[0]), "=r"(r[1]), "=r"(r[2]), "=r"(r[3]) : "r"(addr));
}
__device__ __forceinline__ void mma_fp8(float* c, const unsigned* a,
                                        unsigned b0, unsigned b1) {
    asm volatile(
        "mma.sync.aligned.m16n8k32.row.col.f32.e4m3.e4m3.f32 "
        "{%0,%1,%2,%3}, {%4,%5,%6,%7}, {%8,%9}, {%0,%1,%2,%3};"
        : "+f"(c[0]), "+f"(c[1]), "+f"(c[2]), "+f"(c[3])
        : "r"(a[0]), "r"(a[1]), "r"(a[2]), "r"(a[3]), "r"(b0), "r"(b1));
}
__device__ __forceinline__ float ex2s(float v) {   // exp((v/256 - 1)/tau)
    float y;
    asm("ex2.approx.ftz.f32 %0, %1;" : "=f"(y) : "f"(fmaf(v, EXSC, -K1F)));
    return y;
}
__device__ __forceinline__ unsigned short cvt2_e4m3(float lo, float hi) {
    unsigned short r;
    asm("cvt.rn.satfinite.e4m3x2.f32 %0, %1, %2;" : "=h"(r) : "f"(hi), "f"(lo));
    return r;
}

// decode flattened tile index -> (I, J)
__device__ __forceinline__ void tile_decode(int t, int& I, int& J) {
    int p = t / 65;
    int l = t - p * 65;
    int n1 = 64 - p;
    if (l < n1) { I = p;      J = p + l; }
    else        { I = 63 - p; J = I + (l - n1); }
}

// ------------------------- kernel 1: normalize -> fp8 ----------------------
__global__ __launch_bounds__(256) void ntx_normalize(const float* __restrict__ anchor,
                                                     const float* __restrict__ positive) {
    int gt = blockIdx.x * 256 + threadIdx.x;
    if (gt < NN) g_rowsum[gt] = 0.f;          // graph-replay safe re-init

    int row  = blockIdx.x * 8 + (threadIdx.x >> 5);
    int lane = threadIdx.x & 31;
    const float* src = (row < BHALF) ? (anchor + (size_t)row * DD)
                                     : (positive + (size_t)(row - BHALF) * DD);
    const float4* s4 = (const float4*)src;
    float4 v[4];
    float ss = 0.f;
#pragma unroll
    for (int q = 0; q < 4; q++) {
        v[q] = s4[lane + 32 * q];
        ss += v[q].x * v[q].x + v[q].y * v[q].y + v[q].z * v[q].z + v[q].w * v[q].w;
    }
#pragma unroll
    for (int o = 16; o > 0; o >>= 1) ss += __shfl_xor_sync(0xFFFFFFFFu, ss, o);
    float s16 = 16.0f / fmaxf(sqrtf(ss), 1e-8f);   // unit-norm then x16 for e4m3

    unsigned* zp = (unsigned*)(g_z + (size_t)row * DD);
#pragma unroll
    for (int q = 0; q < 4; q++) {
        unsigned lo = cvt2_e4m3(v[q].x * s16, v[q].y * s16);
        unsigned hi = cvt2_e4m3(v[q].z * s16, v[q].w * s16);
        zp[lane + 32 * q] = lo | (hi << 16);
    }
}

// ------------------------- kernel 2: upper-tri GEMM + exp-reduce -----------
// issue one B chunk (chunk k of column block colbase) into ring slot k
__device__ __forceinline__ void issueB(unsigned bbase, int colbase, int k, int tid) {
#pragma unroll
    for (int it = 0; it < 4; it++) {
        int idx = tid + it * 256;
        int r = idx >> 3, c8 = idx & 7;
        const void* src = g_z + ((size_t)(colbase + r) << 9) + k * 128 + c8 * 16;
        cp16(bbase + swz((unsigned)(r * 128 + c8 * 16)), src);
    }
}

// issue chunk with global chunk id m (relative to t0), if it exists
__device__ __forceinline__ void issue_chunk(unsigned Bb, int t0, int t1, int m, int tid) {
    int tt = t0 + (m >> 2);
    if (tt < t1) {
        int I2, J2;
        tile_decode(tt, I2, J2);
        issueB(Bb + (unsigned)(m & 3) * B_BYTES, J2 << 7, m & 3, tid);
    }
    CP_COMMIT();
}

__global__ __launch_bounds__(256, 1) void ntx_main() {
    extern __shared__ char smem_raw[];
    unsigned raw  = smem_u32(smem_raw);
    unsigned base = (raw + 1023u) & ~1023u;
    char* sp      = smem_raw + (base - raw);   // generic ptr to aligned base
    unsigned A  = base;
    unsigned Bb = base + B_OFF;

    int tid  = threadIdx.x;
    int wid  = tid >> 5, lane = tid & 31;
    int warpM = wid & 3, warpN = wid >> 2;     // 4 x 2 warp grid, tile 32x64
    int qrow = lane >> 2;

    int c  = blockIdx.x;
    int t0 = (c * NTILES) / NCTAS;
    int t1 = ((c + 1) * NTILES) / NCTAS;

    // ldmatrix lane addressing: sel picks (row+8 | k+16) tile, lr is row-in-8
    int sel = lane >> 3, lr = lane & 7;
    unsigned aoff[2][4];
#pragma unroll
    for (int mf = 0; mf < 2; mf++)
#pragma unroll
        for (int ks = 0; ks < 4; ks++) {
            int r = warpM * 32 + mf * 16 + ((sel & 1) << 3) + lr;
            unsigned cb = (unsigned)(ks * 32 + ((sel >> 1) << 4));
            aoff[mf][ks] = (unsigned)(r * 128) + (cb ^ ((unsigned)lr << 4));
        }
    unsigned boff[4][4];
#pragma unroll
    for (int p = 0; p < 4; p++)
#pragma unroll
        for (int ks = 0; ks < 4; ks++) {
            int r = warpN * 64 + p * 16 + ((sel & 1) << 3) + lr;
            unsigned cb = (unsigned)(ks * 32 + ((sel >> 1) << 4));
            boff[p][ks] = (unsigned)(r * 128) + (cb ^ ((unsigned)lr << 4));
        }

    // prologue: prefetch chunks 0..2 of the stream
    issue_chunk(Bb, t0, t1, 0, tid);
    issue_chunk(Bb, t0, t1, 1, tid);
    issue_chunk(Bb, t0, t1, 2, tid);

    float acc[2][8][4];
    float rsum[2][2] = {{0.f, 0.f}, {0.f, 0.f}};
    int curI = -1;
    int cm = 0;                                // consumer chunk counter

    for (int t = t0; t < t1; t++) {
        int I, J;
        tile_decode(t, I, J);
        int rowbase = I << 7, colbase = J << 7;

        if (I != curI) {
            if (curI >= 0) {
#pragma unroll
                for (int mf = 0; mf < 2; mf++)
#pragma unroll
                    for (int h = 0; h < 2; h++) {
                        float v = rsum[mf][h];
                        v += __shfl_xor_sync(0xFFFFFFFFu, v, 1);
                        v += __shfl_xor_sync(0xFFFFFFFFu, v, 2);
                        if ((lane & 3) == 0)
                            atomicAdd(&g_rowsum[(curI << 7) + warpM * 32 + mf * 16 + h * 8 + qrow], v);
                        rsum[mf][h] = 0.f;
                    }
            }
            // A reload via LDG->STS (keeps the B cp.async ring untouched)
            __syncthreads();                   // all readers of old A done
#pragma unroll
            for (int it = 0; it < 16; it++) {
                int x = tid + it * 256;
                int r = x >> 5, u = x & 31, ck = u >> 3, c8 = u & 7;
                const uint4* src = (const uint4*)(g_z + ((size_t)(rowbase + r) << 9)
                                                  + ck * 128 + c8 * 16);
                *(uint4*)(sp + ck * 16384 + swz((unsigned)(r * 128 + c8 * 16))) = *src;
            }
            __syncthreads();
            curI = I;
        }

#pragma unroll
        for (int mf = 0; mf < 2; mf++)
#pragma unroll
            for (int nf = 0; nf < 8; nf++)
#pragma unroll
                for (int e = 0; e < 4; e++) acc[mf][nf][e] = 0.f;

#pragma unroll
        for (int k = 0; k < NCHUNK; k++) {
            CP_WAIT(2);                        // chunk cm landed
            __syncthreads();
            // refill: chunk cm+3 overwrites slot of chunk cm-1 (readers done
            // before the barrier just crossed)
            issue_chunk(Bb, t0, t1, cm + 3, tid);

            unsigned Ac = A + k * 16384;
            unsigned Bc = Bb + k * 16384;      // ring slot == K-chunk index
#pragma unroll
            for (int ks = 0; ks < 4; ks++) {
                unsigned afr[2][4];
                ldsm_x4(afr[0], Ac + aoff[0][ks]);
                ldsm_x4(afr[1], Ac + aoff[1][ks]);
                unsigned bfr[4][4];
#pragma unroll
                for (int p = 0; p < 4; p++) ldsm_x4(bfr[p], Bc + boff[p][ks]);
#pragma unroll
                for (int mf = 0; mf < 2; mf++)
#pragma unroll
                    for (int nf = 0; nf < 8; nf++)
                        mma_fp8(acc[mf][nf], afr[mf],
                                bfr[nf >> 1][nf & 1],
                                bfr[nf >> 1][2 + (nf & 1)]);
            }
            cm++;
        }

        // ---- epilogue (next tile's B chunks are prefetching meanwhile) ----
        bool isdiag = (J == I);
        bool ispos  = (J == I + 32);

        if (isdiag | ispos) {
#pragma unroll
            for (int mf = 0; mf < 2; mf++)
#pragma unroll
                for (int h = 0; h < 2; h++) {
                    int rloc = warpM * 32 + mf * 16 + h * 8 + qrow;
                    int cc = rloc - warpN * 64;
                    if (cc >= 0 && cc < 64 && (((cc >> 1) & 3) == (lane & 3))) {
                        float v = acc[mf][cc >> 3][(h << 1) | (cc & 1)];
                        if (isdiag) rsum[mf][h] -= ex2s(v);
                        if (ispos) {
                            g_pos[rowbase + rloc] = v * PSC;
                            g_pos[rowbase + rloc + BHALF] = v * PSC;
                        }
                    }
                }
        }

        float colp[16];
#pragma unroll
        for (int q = 0; q < 16; q++) colp[q] = 0.f;
#pragma unroll
        for (int mf = 0; mf < 2; mf++) {
            float slo = 0.f, shi = 0.f;
#pragma unroll
            for (int nf = 0; nf < 8; nf++) {
                float e0 = ex2s(acc[mf][nf][0]);
                float e1 = ex2s(acc[mf][nf][1]);
                float e2 = ex2s(acc[mf][nf][2]);
                float e3 = ex2s(acc[mf][nf][3]);
                slo += e0 + e1;
                shi += e2 + e3;
                colp[nf * 2]     += e0 + e2;
                colp[nf * 2 + 1] += e1 + e3;
            }
            rsum[mf][0] += slo;
            rsum[mf][1] += shi;
        }

        if (!isdiag) {
#pragma unroll
            for (int q = 0; q < 16; q++) {
                float v = colp[q];
                v += __shfl_xor_sync(0xFFFFFFFFu, v, 4);
                v += __shfl_xor_sync(0xFFFFFFFFu, v, 8);
                v += __shfl_xor_sync(0xFFFFFFFFu, v, 16);
                if (lane < 4) {
                    int ccol = (q >> 1) * 8 + 2 * lane + (q & 1);
                    atomicAdd(&g_rowsum[colbase + warpN * 64 + ccol], v);
                }
            }
        }
    }

    // final row flush
#pragma unroll
    for (int mf = 0; mf < 2; mf++)
#pragma unroll
        for (int h = 0; h < 2; h++) {
            float v = rsum[mf][h];
            v += __shfl_xor_sync(0xFFFFFFFFu, v, 1);
            v += __shfl_xor_sync(0xFFFFFFFFu, v, 2);
            if ((lane & 3) == 0 && curI >= 0)
                atomicAdd(&g_rowsum[(curI << 7) + warpM * 32 + mf * 16 + h * 8 + qrow], v);
        }
}

// ------------------------- kernel 3: final reduce --------------------------
__global__ __launch_bounds__(1024) void ntx_final(float* __restrict__ out) {
    int tid = threadIdx.x;
    float local = 0.f;
    for (int r = tid; r < NN; r += 1024) {
        local += (1.0f - g_pos[r]) * INV_TAU + __logf(g_rowsum[r]);
    }
#pragma unroll
    for (int o = 16; o > 0; o >>= 1) local += __shfl_xor_sync(0xFFFFFFFFu, local, o);
    __shared__ float red[32];
    if ((tid & 31) == 0) red[tid >> 5] = local;
    __syncthreads();
    if (tid < 32) {
        float v = red[tid];
#pragma unroll
        for (int o = 16; o > 0; o >>= 1) v += __shfl_xor_sync(0xFFFFFFFFu, v, o);
        if (tid == 0) out[0] = v * (1.0f / (float)NN);
    }
}

// ---------------------------------------------------------------------------
extern "C" void kernel_launch(void* const* d_in, const int* in_sizes, int n_in,
                              void* d_out, int out_size) {
    (void)in_sizes; (void)n_in; (void)out_size;
    const float* anchor   = (const float*)d_in[0];
    const float* positive = (const float*)d_in[1];

    cudaFuncSetAttribute(ntx_main, cudaFuncAttributeMaxDynamicSharedMemorySize,
                         SMEM_BYTES);

    ntx_normalize<<<NN / 8, 256>>>(anchor, positive);
    ntx_main<<<NCTAS, 256, SMEM_BYTES>>>();
    ntx_final<<<1, 1024>>>((float*)d_out);
}

// round 7
// speedup vs baseline: 2.6367x; 1.0260x over previous
#include <cuda_runtime.h>
#include <cuda_bf16.h>

// ---------------------------------------------------------------------------
// NT-Xent loss, N=8192, D=512. FP8 (e4m3, scale 16) mma.sync m16n8k32,
// upper-triangular block tiles only (S = Z Z^T symmetric).
// Tile (I,J), J>I: exp-row-sums -> rows of block I, exp-col-sums -> block J.
// loss_i = (1 - pos_i)/tau + log( sum_{j != i} exp((dot_ij - 1)/tau) )
// 2080 tiles across 296 CTAs, 2 CTAs/SM (96 KB smem, <=128 regs) so one
// CTA's epilogue/barriers overlap the other's tensor work.
// ---------------------------------------------------------------------------

#define NN      8192
#define DD      512
#define BHALF   4096
#define NCHUNK  4            // 512 fp8 bytes / 128-byte chunk
#define NTILES  2080
#define NCTAS   296

#define K1F     20.60992915555662f        // log2(e)/0.07
#define EXSC    0.08050753576389304f      // K1F / 256   (fp8 scale^2)
#define PSC     0.00390625f               // 1/256
#define INV_TAU 14.285714285714286f

#define A_BYTES  65536       // 128 rows x 512 B (4 chunks x 16 KB)
#define B_OFF    65536
#define B_BYTES  16384       // one B chunk: 128 rows x 128 B
#define SMEM_BYTES (A_BYTES + 2*B_BYTES + 1024)

__device__ __align__(128) unsigned char g_z[(size_t)NN * DD];   // e4m3, x16
__device__ float g_rowsum[NN];
__device__ float g_pos[NN];

// ------------------------------- helpers -----------------------------------
__device__ __forceinline__ unsigned smem_u32(const void* p) {
    unsigned a;
    asm("{ .reg .u64 t; cvta.to.shared.u64 t, %1; cvt.u32.u64 %0, t; }"
        : "=r"(a) : "l"(p));
    return a;
}
__device__ __forceinline__ unsigned swz(unsigned off) {
    return off ^ ((off >> 3) & 0x70);
}
__device__ __forceinline__ void cp16(unsigned dst, const void* src) {
    asm volatile("cp.async.cg.shared.global [%0], [%1], 16;"
                 :: "r"(dst), "l"(src) : "memory");
}
#define CP_COMMIT() asm volatile("cp.async.commit_group;" ::: "memory")
#define CP_WAIT(n)  asm volatile("cp.async.wait_group %0;" :: "n"(n) : "memory")

__device__ __forceinline__ void ldsm_x4(unsigned* r, unsigned addr) {
    asm volatile("ldmatrix.sync.aligned.m8n8.x4.shared.b16 {%0,%1,%2,%3}, [%4];"
                 : "=r"(r[0]), "=r"(r[1]), "=r"(r[2]), "=r"(r[3]) : "r"(addr));
}
__device__ __forceinline__ void mma_fp8(float* c, const unsigned* a,
                                        unsigned b0, unsigned b1) {
    asm volatile(
        "mma.sync.aligned.m16n8k32.row.col.f32.e4m3.e4m3.f32 "
        "{%0,%1,%2,%3}, {%4,%5,%6,%7}, {%8,%9}, {%0,%1,%2,%3};"
        : "+f"(c[0]), "+f"(c[1]), "+f"(c[2]), "+f"(c[3])
        : "r"(a[0]), "r"(a[1]), "r"(a[2]), "r"(a[3]), "r"(b0), "r"(b1));
}
__device__ __forceinline__ float ex2s(float v) {   // exp((v/256 - 1)/tau)
    float y;
    asm("ex2.approx.ftz.f32 %0, %1;" : "=f"(y) : "f"(fmaf(v, EXSC, -K1F)));
    return y;
}
__device__ __forceinline__ unsigned short cvt2_e4m3(float lo, float hi) {
    unsigned short r;
    asm("cvt.rn.satfinite.e4m3x2.f32 %0, %1, %2;" : "=h"(r) : "f"(hi), "f"(lo));
    return r;
}

// decode flattened tile index -> (I, J)
__device__ __forceinline__ void tile_decode(int t, int& I, int& J) {
    int p = t / 65;
    int l = t - p * 65;
    int n1 = 64 - p;
    if (l < n1) { I = p;      J = p + l; }
    else        { I = 63 - p; J = I + (l - n1); }
}

// ------------------------- kernel 1: normalize -> fp8 ----------------------
__global__ __launch_bounds__(256) void ntx_normalize(const float* __restrict__ anchor,
                                                     const float* __restrict__ positive) {
    int gt = blockIdx.x * 256 + threadIdx.x;
    if (gt < NN) g_rowsum[gt] = 0.f;          // graph-replay safe re-init

    int row  = blockIdx.x * 8 + (threadIdx.x >> 5);
    int lane = threadIdx.x & 31;
    const float* src = (row < BHALF) ? (anchor + (size_t)row * DD)
                                     : (positive + (size_t)(row - BHALF) * DD);
    const float4* s4 = (const float4*)src;
    float4 v[4];
    float ss = 0.f;
#pragma unroll
    for (int q = 0; q < 4; q++) {
        v[q] = s4[lane + 32 * q];
        ss += v[q].x * v[q].x + v[q].y * v[q].y + v[q].z * v[q].z + v[q].w * v[q].w;
    }
#pragma unroll
    for (int o = 16; o > 0; o >>= 1) ss += __shfl_xor_sync(0xFFFFFFFFu, ss, o);
    float s16 = 16.0f / fmaxf(sqrtf(ss), 1e-8f);   // unit-norm then x16 for e4m3

    unsigned* zp = (unsigned*)(g_z + (size_t)row * DD);
#pragma unroll
    for (int q = 0; q < 4; q++) {
        unsigned lo = cvt2_e4m3(v[q].x * s16, v[q].y * s16);
        unsigned hi = cvt2_e4m3(v[q].z * s16, v[q].w * s16);
        zp[lane + 32 * q] = lo | (hi << 16);
    }
}

// ------------------------- kernel 2: upper-tri GEMM + exp-reduce -----------
// issue one B chunk (chunk k of column block colbase) into ring slot
__device__ __forceinline__ void issueB(unsigned bbase, int colbase, int k, int tid) {
#pragma unroll
    for (int it = 0; it < 4; it++) {
        int idx = tid + it * 256;
        int r = idx >> 3, c8 = idx & 7;
        const void* src = g_z + ((size_t)(colbase + r) << 9) + k * 128 + c8 * 16;
        cp16(bbase + swz((unsigned)(r * 128 + c8 * 16)), src);
    }
}

// issue chunk with global chunk id m (relative to t0), if it exists.
// ring depth 2: slot = m & 1
__device__ __forceinline__ void issue_chunk(unsigned Bb, int t0, int t1, int m, int tid) {
    int tt = t0 + (m >> 2);
    if (tt < t1) {
        int I2, J2;
        tile_decode(tt, I2, J2);
        issueB(Bb + (unsigned)(m & 1) * B_BYTES, J2 << 7, m & 3, tid);
    }
    CP_COMMIT();
}

__global__ __launch_bounds__(256, 2) void ntx_main() {
    extern __shared__ char smem_raw[];
    unsigned raw  = smem_u32(smem_raw);
    unsigned base = (raw + 1023u) & ~1023u;
    char* sp      = smem_raw + (base - raw);   // generic ptr to aligned base
    unsigned A  = base;
    unsigned Bb = base + B_OFF;

    int tid  = threadIdx.x;
    int wid  = tid >> 5, lane = tid & 31;
    int warpM = wid & 3, warpN = wid >> 2;     // 4 x 2 warp grid, tile 32x64
    int qrow = lane >> 2;

    int c  = blockIdx.x;
    int t0 = (c * NTILES) / NCTAS;
    int t1 = ((c + 1) * NTILES) / NCTAS;

    // ldmatrix lane addressing: sel picks (row+8 | k+16) tile, lr is row-in-8
    int sel = lane >> 3, lr = lane & 7;
    unsigned aoff[2][4];
#pragma unroll
    for (int mf = 0; mf < 2; mf++)
#pragma unroll
        for (int ks = 0; ks < 4; ks++) {
            int r = warpM * 32 + mf * 16 + ((sel & 1) << 3) + lr;
            unsigned cb = (unsigned)(ks * 32 + ((sel >> 1) << 4));
            aoff[mf][ks] = (unsigned)(r * 128) + (cb ^ ((unsigned)lr << 4));
        }
    unsigned boff[4][4];
#pragma unroll
    for (int p = 0; p < 4; p++)
#pragma unroll
        for (int ks = 0; ks < 4; ks++) {
            int r = warpN * 64 + p * 16 + ((sel & 1) << 3) + lr;
            unsigned cb = (unsigned)(ks * 32 + ((sel >> 1) << 4));
            boff[p][ks] = (unsigned)(r * 128) + (cb ^ ((unsigned)lr << 4));
        }

    // prologue: prefetch chunk 0
    issue_chunk(Bb, t0, t1, 0, tid);

    float acc[2][8][4];
    float rsum[2][2] = {{0.f, 0.f}, {0.f, 0.f}};
    int curI = -1;
    int cm = 0;                                // consumer chunk counter

    for (int t = t0; t < t1; t++) {
        int I, J;
        tile_decode(t, I, J);
        int rowbase = I << 7, colbase = J << 7;

        if (I != curI) {
            if (curI >= 0) {
#pragma unroll
                for (int mf = 0; mf < 2; mf++)
#pragma unroll
                    for (int h = 0; h < 2; h++) {
                        float v = rsum[mf][h];
                        v += __shfl_xor_sync(0xFFFFFFFFu, v, 1);
                        v += __shfl_xor_sync(0xFFFFFFFFu, v, 2);
                        if ((lane & 3) == 0)
                            atomicAdd(&g_rowsum[(curI << 7) + warpM * 32 + mf * 16 + h * 8 + qrow], v);
                        rsum[mf][h] = 0.f;
                    }
            }
            // A reload via LDG->STS (keeps the B cp.async ring untouched)
            __syncthreads();                   // all readers of old A done
#pragma unroll
            for (int it = 0; it < 16; it++) {
                int x = tid + it * 256;
                int r = x >> 5, u = x & 31, ck = u >> 3, c8 = u & 7;
                const uint4* src = (const uint4*)(g_z + ((size_t)(rowbase + r) << 9)
                                                  + ck * 128 + c8 * 16);
                *(uint4*)(sp + ck * 16384 + swz((unsigned)(r * 128 + c8 * 16))) = *src;
            }
            __syncthreads();
            curI = I;
        }

#pragma unroll
        for (int mf = 0; mf < 2; mf++)
#pragma unroll
            for (int nf = 0; nf < 8; nf++)
#pragma unroll
                for (int e = 0; e < 4; e++) acc[mf][nf][e] = 0.f;

#pragma unroll
        for (int k = 0; k < NCHUNK; k++) {
            CP_WAIT(0);                        // chunk cm landed
            __syncthreads();
            // refill: chunk cm+1 overwrites slot of chunk cm-1 (its readers
            // all finished before the barrier just crossed)
            issue_chunk(Bb, t0, t1, cm + 1, tid);

            unsigned Ac = A + k * 16384;
            unsigned Bc = Bb + (unsigned)(cm & 1) * B_BYTES;
#pragma unroll
            for (int ks = 0; ks < 4; ks++) {
                unsigned afr[2][4];
                ldsm_x4(afr[0], Ac + aoff[0][ks]);
                ldsm_x4(afr[1], Ac + aoff[1][ks]);
                unsigned bfr[4][4];
#pragma unroll
                for (int p = 0; p < 4; p++) ldsm_x4(bfr[p], Bc + boff[p][ks]);
#pragma unroll
                for (int mf = 0; mf < 2; mf++)
#pragma unroll
                    for (int nf = 0; nf < 8; nf++)
                        mma_fp8(acc[mf][nf], afr[mf],
                                bfr[nf >> 1][nf & 1],
                                bfr[nf >> 1][2 + (nf & 1)]);
            }
            cm++;
        }

        // ---- epilogue (partner CTA's MMAs cover this on the same SM) ----
        bool isdiag = (J == I);
        bool ispos  = (J == I + 32);

        if (isdiag | ispos) {
#pragma unroll
            for (int mf = 0; mf < 2; mf++)
#pragma unroll
                for (int h = 0; h < 2; h++) {
                    int rloc = warpM * 32 + mf * 16 + h * 8 + qrow;
                    int cc = rloc - warpN * 64;
                    if (cc >= 0 && cc < 64 && (((cc >> 1) & 3) == (lane & 3))) {
                        float v = acc[mf][cc >> 3][(h << 1) | (cc & 1)];
                        if (isdiag) rsum[mf][h] -= ex2s(v);
                        if (ispos) {
                            g_pos[rowbase + rloc] = v * PSC;
                            g_pos[rowbase + rloc + BHALF] = v * PSC;
                        }
                    }
                }
        }

        float colp[16];
#pragma unroll
        for (int q = 0; q < 16; q++) colp[q] = 0.f;
#pragma unroll
        for (int mf = 0; mf < 2; mf++) {
            float slo = 0.f, shi = 0.f;
#pragma unroll
            for (int nf = 0; nf < 8; nf++) {
                float e0 = ex2s(acc[mf][nf][0]);
                float e1 = ex2s(acc[mf][nf][1]);
                float e2 = ex2s(acc[mf][nf][2]);
                float e3 = ex2s(acc[mf][nf][3]);
                slo += e0 + e1;
                shi += e2 + e3;
                colp[nf * 2]     += e0 + e2;
                colp[nf * 2 + 1] += e1 + e3;
            }
            rsum[mf][0] += slo;
            rsum[mf][1] += shi;
        }

        if (!isdiag) {
#pragma unroll
            for (int q = 0; q < 16; q++) {
                float v = colp[q];
                v += __shfl_xor_sync(0xFFFFFFFFu, v, 4);
                v += __shfl_xor_sync(0xFFFFFFFFu, v, 8);
                v += __shfl_xor_sync(0xFFFFFFFFu, v, 16);
                if (lane < 4) {
                    int ccol = (q >> 1) * 8 + 2 * lane + (q & 1);
                    atomicAdd(&g_rowsum[colbase + warpN * 64 + ccol], v);
                }
            }
        }
    }

    // final row flush
#pragma unroll
    for (int mf = 0; mf < 2; mf++)
#pragma unroll
        for (int h = 0; h < 2; h++) {
            float v = rsum[mf][h];
            v += __shfl_xor_sync(0xFFFFFFFFu, v, 1);
            v += __shfl_xor_sync(0xFFFFFFFFu, v, 2);
            if ((lane & 3) == 0 && curI >= 0)
                atomicAdd(&g_rowsum[(curI << 7) + warpM * 32 + mf * 16 + h * 8 + qrow], v);
        }
}

// ------------------------- kernel 3: final reduce --------------------------
__global__ __launch_bounds__(1024) void ntx_final(float* __restrict__ out) {
    int tid = threadIdx.x;
    float local = 0.f;
    for (int r = tid; r < NN; r += 1024) {
        local += (1.0f - g_pos[r]) * INV_TAU + __logf(g_rowsum[r]);
    }
#pragma unroll
    for (int o = 16; o > 0; o >>= 1) local += __shfl_xor_sync(0xFFFFFFFFu, local, o);
    __shared__ float red[32];
    if ((tid & 31) == 0) red[tid >> 5] = local;
    __syncthreads();
    if (tid < 32) {
        float v = red[tid];
#pragma unroll
        for (int o = 16; o > 0; o >>= 1) v += __shfl_xor_sync(0xFFFFFFFFu, v, o);
        if (tid == 0) out[0] = v * (1.0f / (float)NN);
    }
}

// ---------------------------------------------------------------------------
extern "C" void kernel_launch(void* const* d_in, const int* in_sizes, int n_in,
                              void* d_out, int out_size) {
    (void)in_sizes; (void)n_in; (void)out_size;
    const float* anchor   = (const float*)d_in[0];
    const float* positive = (const float*)d_in[1];

    cudaFuncSetAttribute(ntx_main, cudaFuncAttributeMaxDynamicSharedMemorySize,
                         SMEM_BYTES);

    ntx_normalize<<<NN / 8, 256>>>(anchor, positive);
    ntx_main<<<NCTAS, 256, SMEM_BYTES>>>();
    ntx_final<<<1, 1024>>>((float*)d_out);
}